// round 16
// baseline (speedup 1.0000x reference)
#include <cuda_runtime.h>

#define T_STEPS 4096
#define NCTA    128
#define NTHR    512

typedef unsigned long long ull;

// ---------------- global scratch (static; no allocs) ----------------
// h layout: [slot][mpair 0..127][b 0..63][2] -> element (m,b) at [m>>1][b][m&1]
__device__ __align__(256) float g_h0[2][128][64][2];     // h0(s) at slot s&1
__device__ __align__(256) float g_h1[4098][128][64][2];  // h1(s) at slot s+2; slots 0,1 zero
__device__ __align__(256) float g_yT[4099][64];          // yT[t+3][b] = y[b][t]; rows 0..2 pad
__device__ __align__(256) unsigned g_afl[NCTA];  // arrival flags; 0 between runs
__device__ unsigned g_go;     // release word; 0 between runs
__device__ unsigned g_cnt;    // legacy barrier; 0 between runs
__device__ unsigned g_sense;  // legacy barrier; 2 teardown rounds -> returns to 0

// ---------------- helpers ----------------
__device__ __forceinline__ ull ffma2(ull h, ull w, ull a) {
    ull d;
    asm("fma.rn.f32x2 %0, %1, %2, %3;" : "=l"(d) : "l"(h), "l"(w), "l"(a));
    return d;
}
__device__ __forceinline__ float collapse2(ull a) {   // even-m sum + odd-m sum
    return __uint_as_float((unsigned)a) + __uint_as_float((unsigned)(a >> 32));
}
__device__ __forceinline__ float sigf(float x)   { return 1.0f / (1.0f + __expf(-x)); }
__device__ __forceinline__ float tanh_f(float x) { return 2.0f * sigf(2.0f * x) - 1.0f; }

__device__ __forceinline__ ulonglong2 ldcg2(const float* p) {
    ulonglong2 v;
    asm volatile("ld.global.cg.v2.u64 {%0,%1}, [%2];" : "=l"(v.x), "=l"(v.y) : "l"(p));
    return v;
}
__device__ __forceinline__ unsigned atom_add_acqrel(unsigned* p, unsigned v) {
    unsigned old;
    asm volatile("atom.acq_rel.gpu.global.add.u32 %0, [%1], %2;"
                 : "=r"(old) : "l"(p), "r"(v) : "memory");
    return old;
}
__device__ __forceinline__ unsigned ld_acquire(const unsigned* p) {
    unsigned v;
    asm volatile("ld.acquire.gpu.global.u32 %0, [%1];" : "=r"(v) : "l"(p) : "memory");
    return v;
}
__device__ __forceinline__ uint4 ld_relaxed_v4(const unsigned* p) {
    uint4 v;
    asm volatile("ld.relaxed.gpu.global.v4.u32 {%0,%1,%2,%3}, [%4];"
                 : "=r"(v.x), "=r"(v.y), "=r"(v.z), "=r"(v.w) : "l"(p) : "memory");
    return v;
}
__device__ __forceinline__ void st_release(unsigned* p, unsigned v) {
    asm volatile("st.release.gpu.global.u32 [%0], %1;" :: "l"(p), "r"(v) : "memory");
}
__device__ __forceinline__ void st_relaxed(unsigned* p, unsigned v) {
    asm volatile("st.relaxed.gpu.global.u32 [%0], %1;" :: "l"(p), "r"(v) : "memory");
}
__device__ __forceinline__ void fence_acqrel_gpu() {
    asm volatile("fence.acq_rel.gpu;" ::: "memory");
}

// funnel-free two-level flag barrier; rn is a monotone round number (>=1)
__device__ __forceinline__ void flag_barrier(int tid, int bid, unsigned rn) {
    __syncthreads();
    if (tid == 0) st_release(&g_afl[bid], rn);       // parallel arrivals (no atomics)
    if (bid == 0) {
        if (tid < 32) {                              // one warp aggregates all 128 flags
            const unsigned* fp = g_afl + tid * 4;
            for (;;) {
                uint4 v = ld_relaxed_v4(fp);
                bool ok = (v.x >= rn) & (v.y >= rn) & (v.z >= rn) & (v.w >= rn);
                if (__all_sync(0xffffffffu, ok)) break;
            }
            if (tid == 0) { fence_acqrel_gpu(); st_release(&g_go, rn); }
        }
    } else {
        if (tid == 0) {
            while (ld_acquire(&g_go) < rn) { }
        }
    }
    __syncthreads();
}

// legacy atomic barrier — used exactly twice at teardown (resets itself)
__device__ __forceinline__ void grid_barrier(int tid, unsigned& ls) {
    __syncthreads();
    ls ^= 1u;
    if (tid == 0) {
        unsigned old = atom_add_acqrel(&g_cnt, 1u);
        if (old == NCTA - 1u) {
            st_relaxed(&g_cnt, 0u);
            st_release(&g_sense, ls);
        } else {
            while (ld_acquire(&g_sense) != ls) { }
        }
    }
    __syncthreads();
}

// ---------------- smem layout (floats) ----------------
//   W0s [32][256]    @ 0      (8192)  W_hh0 rows (lr = gate*8+u), fp32 K-major
//   W1s [32][256]    @ 8192   (8192)  W_ih1
//   WHs [32][256]    @ 16384  (8192)  W_hh1
//   P0  [16][32][16] @ 24576  (8192)  layer0 gate partials (q, lr, local batch)
//   P1  [16][32][16] @ 32768  (8192)
//   Rg  [2][32][16]  @ 40960  (1024)  reduced gates
//   misc @ 41984: wih0[32][4]=128, b0s[32], b1s[32], yw[4][16]=64, wout[512], bo2[2]
#define SMEM_FLOATS (41984 + 770)
#define SMEM_BYTES  (SMEM_FLOATS * 4)

__global__ void __launch_bounds__(NTHR, 1) lstm_all(
    const float* __restrict__ y,
    const float* __restrict__ Wih0, const float* __restrict__ Whh0,
    const float* __restrict__ bih0, const float* __restrict__ bhh0,
    const float* __restrict__ Wih1, const float* __restrict__ Whh1,
    const float* __restrict__ bih1, const float* __restrict__ bhh1,
    const float* __restrict__ Wout, const float* __restrict__ bout,
    float* __restrict__ out)
{
    extern __shared__ float sm[];
    float* W0s  = sm;              // [32][256]
    float* W1s  = sm + 8192;
    float* WHs  = sm + 16384;
    float* P0   = sm + 24576;      // [16][32][16]
    float* P1   = sm + 32768;
    float* Rg   = sm + 40960;      // [2][32][16]
    float* wih0 = sm + 41984;      // [32][4]
    float* b0s  = wih0 + 128;      // [32]
    float* b1s  = b0s + 32;        // [32]
    float* yw   = b1s + 32;        // [4][16]
    float* wout = yw + 64;         // [2][256]
    float* bo2  = wout + 512;      // [2]

    const int tid = threadIdx.x;
    const int bid = blockIdx.x;
    const int j0  = (bid & 31) * 8;          // CTA owns hidden units j0..j0+7
    const int B0  = (bid >> 5) * 16;         // CTA owns batches B0..B0+15
    unsigned ls = 0;

    // ======== init: global state ========
    {
        int gi = bid * NTHR + tid;           // 0..65535
        if (gi < 32768) {
            ((float*)g_h0)[gi] = 0.0f;       // both h0 slots
            ((float*)g_h1)[gi] = 0.0f;       // h1 slots 0,1
        }
        for (int i = gi; i < 4099 * 64; i += NCTA * NTHR) {
            int row = i >> 6, b = i & 63;
            g_yT[row][b] = (row < 3) ? -100.0f : y[b * T_STEPS + (row - 3)];
        }
    }

    // ======== init: smem weights (plain fp32 rows; lr = gate*8 + u) ========
    for (int idx = tid; idx < 32 * 256; idx += NTHR) {
        int lr = idx >> 8, m = idx & 255;
        int row = (lr >> 3) * 256 + j0 + (lr & 7);
        W0s[idx] = Whh0[row * 256 + m];
        W1s[idx] = Wih1[row * 256 + m];
        WHs[idx] = Whh1[row * 256 + m];
    }
    if (tid < 32) {
        int row = (tid >> 3) * 256 + j0 + (tid & 7);
        b0s[tid] = bih0[row] + bhh0[row];
        b1s[tid] = bih1[row] + bhh1[row];
        for (int k = 0; k < 4; k++) wih0[tid * 4 + k] = Wih0[row * 4 + k];
    }
    wout[tid & 511] = Wout[tid & 511];
    if (tid < 2) bo2[tid] = bout[tid];
    flag_barrier(tid, bid, 1u);              // round 1

    // ======== persistent 2-layer LSTM ========
    const int q    = tid >> 5;               // warp id = m-chunk (16 m per chunk)
    const int lane = tid & 31;
    const int bp   = lane & 7;               // local batch pair (batches 2bp,2bp+1)
    const int rr   = lane >> 3;              // gate 0..3 -> rows rr*8..rr*8+7
    const float* W0r = W0s + rr * 8 * 256 + q * 16;   // + u*256 + mp2*4
    const float* W1r = W1s + rr * 8 * 256 + q * 16;
    const float* WHr = WHs + rr * 8 * 256 + q * 16;
    const int hfl = q * 8 * 128 + (B0 + 2 * bp) * 2;  // float offset of first K-pair

    // cell-update role (first 256 threads; c lives in a register)
    const int clay = tid >> 7;               // 0/1 for tid<256
    const int cu   = (tid >> 4) & 7;         // unit
    const int clb  = tid & 15;               // local batch
    float creg = 0.0f;

    for (int p = 0; p <= T_STEPS; p++) {
        const float* H0 = &g_h0[(p + 1) & 1][0][0][0] + hfl;  // h0(p-1)
        const float* H1 = &g_h1[p][0][0][0] + hfl;            // h1(p-2)
        if (tid < 64 && p < T_STEPS) yw[tid] = g_yT[p + (tid >> 4)][B0 + (tid & 15)];

        // h regs: [i].x = batch even K-pair, [i].y = batch odd K-pair (mp = q*8+i)
        ulonglong2 h0r[8], h1r[8];
        #pragma unroll
        for (int i = 0; i < 8; i++) h0r[i] = ldcg2(H0 + i * 128);
        #pragma unroll
        for (int i = 0; i < 8; i++) h1r[i] = ldcg2(H1 + i * 128);

        // ---- layer0: gate rr, 8 units, 16 m, 2 batches ----
        {
            ull aA[8], aB[8];
            #pragma unroll
            for (int u = 0; u < 8; u++) { aA[u] = 0ull; aB[u] = 0ull; }
            #pragma unroll
            for (int mp2 = 0; mp2 < 4; mp2++) {
                const ulonglong2 hE = h0r[2 * mp2], hO = h0r[2 * mp2 + 1];
                #pragma unroll
                for (int u = 0; u < 8; u++) {
                    ulonglong2 wv = *(const ulonglong2*)(W0r + u * 256 + mp2 * 4);
                    aA[u] = ffma2(hE.x, wv.x, aA[u]);
                    aB[u] = ffma2(hE.y, wv.x, aB[u]);
                    aA[u] = ffma2(hO.x, wv.y, aA[u]);
                    aB[u] = ffma2(hO.y, wv.y, aB[u]);
                }
            }
            #pragma unroll
            for (int u = 0; u < 8; u++) {
                float2 v = make_float2(collapse2(aA[u]), collapse2(aB[u]));
                *(float2*)(P0 + q * 512 + (rr * 8 + u) * 16 + 2 * bp) = v;
            }
        }
        // ---- layer1: W_ih1 x h0(p-1) + W_hh1 x h1(p-2) ----
        {
            ull aA[8], aB[8];
            #pragma unroll
            for (int u = 0; u < 8; u++) { aA[u] = 0ull; aB[u] = 0ull; }
            #pragma unroll
            for (int mp2 = 0; mp2 < 4; mp2++) {
                const ulonglong2 hE = h0r[2 * mp2], hO = h0r[2 * mp2 + 1];
                #pragma unroll
                for (int u = 0; u < 8; u++) {
                    ulonglong2 wv = *(const ulonglong2*)(W1r + u * 256 + mp2 * 4);
                    aA[u] = ffma2(hE.x, wv.x, aA[u]);
                    aB[u] = ffma2(hE.y, wv.x, aB[u]);
                    aA[u] = ffma2(hO.x, wv.y, aA[u]);
                    aB[u] = ffma2(hO.y, wv.y, aB[u]);
                }
            }
            #pragma unroll
            for (int mp2 = 0; mp2 < 4; mp2++) {
                const ulonglong2 hE = h1r[2 * mp2], hO = h1r[2 * mp2 + 1];
                #pragma unroll
                for (int u = 0; u < 8; u++) {
                    ulonglong2 wv = *(const ulonglong2*)(WHr + u * 256 + mp2 * 4);
                    aA[u] = ffma2(hE.x, wv.x, aA[u]);
                    aB[u] = ffma2(hE.y, wv.x, aB[u]);
                    aA[u] = ffma2(hO.x, wv.y, aA[u]);
                    aB[u] = ffma2(hO.y, wv.y, aB[u]);
                }
            }
            #pragma unroll
            for (int u = 0; u < 8; u++) {
                float2 v = make_float2(collapse2(aA[u]), collapse2(aB[u]));
                *(float2*)(P1 + q * 512 + (rr * 8 + u) * 16 + 2 * bp) = v;
            }
        }
        __syncthreads();

        // ---- reduce 16 q-partials -> Rg (each thread: 2 gate sums) ----
        #pragma unroll
        for (int cc = 0; cc < 2; cc++) {
            int c  = tid + cc * 512;
            int ly = c >> 9;
            int r  = (c >> 4) & 31;
            int lb = c & 15;
            const float* P = ly ? P1 : P0;
            float s = ly ? b1s[r] : b0s[r];
            #pragma unroll
            for (int qq = 0; qq < 16; qq++)
                s += P[qq * 512 + r * 16 + lb];
            if (!ly) {
                #pragma unroll
                for (int k = 0; k < 4; k++)
                    s = fmaf(yw[k * 16 + lb], wih0[r * 4 + k], s);
            }
            Rg[ly * 512 + r * 16 + lb] = s;
        }
        __syncthreads();

        // ---- cell update + publish h (first 256 threads) ----
        if (tid < 256) {
            const bool act = clay ? (p > 0) : (p < T_STEPS);
            if (act) {
                float gi = Rg[clay * 512 + (0 * 8 + cu) * 16 + clb];
                float gf = Rg[clay * 512 + (1 * 8 + cu) * 16 + clb];
                float gg = Rg[clay * 512 + (2 * 8 + cu) * 16 + clb];
                float go = Rg[clay * 512 + (3 * 8 + cu) * 16 + clb];
                creg = sigf(gf) * creg + sigf(gi) * tanh_f(gg);
                float h = sigf(go) * tanh_f(creg);
                int j = j0 + cu, b = B0 + clb;
                if (clay == 0) g_h0[p & 1][j >> 1][b][j & 1] = h;   // h0(p)
                else           g_h1[p + 1][j >> 1][b][j & 1] = h;   // h1(p-1)
            }
        }
        flag_barrier(tid, bid, (unsigned)(p + 2));   // rounds 2..4098 (monotone)
    }

    // ======== teardown: reset flag state, legacy barriers return to 0 ========
    grid_barrier(tid, ls);                       // everyone past final flag use
    if (tid == 0) {
        st_relaxed(&g_afl[bid], 0u);             // reset own flag for next replay
        if (bid == 0) st_relaxed(&g_go, 0u);
    }
    grid_barrier(tid, ls);                       // 2 rounds -> g_sense back to 0

    // ======== output projection: out[b][t][k] = h1(t).Wout[k] + bout[k] ========
    {
        const int b  = tid & 63;
        const int tt = tid >> 6;    // 0..7
        #pragma unroll
        for (int u = 0; u < 4; u++) {
            int t = bid * 32 + tt * 4 + u;
            const float* h = &g_h1[t + 2][0][0][0] + b * 2;
            float s0 = bo2[0], s1 = bo2[1];
            #pragma unroll 8
            for (int mp = 0; mp < 128; mp++) {
                float2 v = *(const float2*)(h + mp * 128);
                s0 = fmaf(v.x, wout[2 * mp],       s0);
                s0 = fmaf(v.y, wout[2 * mp + 1],   s0);
                s1 = fmaf(v.x, wout[256 + 2 * mp], s1);
                s1 = fmaf(v.y, wout[257 + 2 * mp], s1);
            }
            out[b * (T_STEPS * 2) + t * 2 + 0] = s0;
            out[b * (T_STEPS * 2) + t * 2 + 1] = s1;
        }
    }
}

// ---------------- launcher: ONE kernel ----------------
extern "C" void kernel_launch(void* const* d_in, const int* in_sizes, int n_in,
                              void* d_out, int out_size)
{
    (void)in_sizes; (void)n_in; (void)out_size;
    cudaFuncSetAttribute(lstm_all, cudaFuncAttributeMaxDynamicSharedMemorySize, SMEM_BYTES);
    lstm_all<<<NCTA, NTHR, SMEM_BYTES>>>(
        (const float*)d_in[0],
        (const float*)d_in[1], (const float*)d_in[2],
        (const float*)d_in[3], (const float*)d_in[4],
        (const float*)d_in[5], (const float*)d_in[6],
        (const float*)d_in[7], (const float*)d_in[8],
        (const float*)d_in[9], (const float*)d_in[10],
        (float*)d_out);
}